// round 2
// baseline (speedup 1.0000x reference)
#include <cuda_runtime.h>
#include <math.h>

#define N_BINS 1024
#define NMASK  (N_BINS - 1)
#define DIM    512
#define DIM4   128           // DIM / 4 (float4 units)
#define NSTEPS 240
#define NK     122           // k in [-61, 60]
#define TI     8             // bins per block in kernel A
#define WIN    (TI + NK - 1) // 129 Q rows per block window
#define NBLK   (N_BINS / TI) // 128 xcorr blocks

// Scratch (device globals; no allocations allowed)
__device__ float g_Q2[N_BINS];
__device__ float g_A[N_BINS];
__device__ float g_bpart[NSTEPS * NBLK];   // per-(step, block) partial sums
__device__ float g_dummy_sink;             // unused

__device__ __forceinline__ float dot4(float4 a, float4 b) {
    return a.x * b.x + a.y * b.y + a.z * b.z + a.w * b.w;
}

// ---------------------------------------------------------------------------
// Kernel 0: Q-row stats only.  Q2[j] = |Q[j]|^2,  A[j] = Q[j].Q[j-1]
// 256 blocks x 256 threads, 2 warps (64 lanes... ) -> simpler: 1024 blocks/64thr
// ---------------------------------------------------------------------------
__global__ void k_rowstats(const float* __restrict__ Dq) {
    int j = blockIdx.x;
    int tid = threadIdx.x;  // 64 threads = 2 warps
    const float4* q  = (const float4*)Dq + j * DIM4;
    const float4* qm = (const float4*)Dq + ((j - 1) & NMASK) * DIM4;
    float s_q2 = 0.f, s_a = 0.f;
    #pragma unroll
    for (int c = tid; c < DIM4; c += 64) {
        float4 qv = q[c], qmv = qm[c];
        s_q2 += dot4(qv, qv);
        s_a  += dot4(qv, qmv);
    }
    #pragma unroll
    for (int off = 16; off; off >>= 1) {
        s_q2 += __shfl_xor_sync(0xffffffffu, s_q2, off);
        s_a  += __shfl_xor_sync(0xffffffffu, s_a,  off);
    }
    __shared__ float r[2][2];
    int w = tid >> 5;
    if ((tid & 31) == 0) { r[0][w] = s_q2; r[1][w] = s_a; }
    __syncthreads();
    if (tid == 0) { g_Q2[j] = r[0][0] + r[0][1]; g_A[j] = r[1][0] + r[1][1]; }
}

// ---------------------------------------------------------------------------
// Kernel A: banded cross-correlation X[i,k] = P[i].Q[(i-k) mod N], k in [-61,60]
// for an 8-bin tile, 2-row batching for smem-traffic reuse, then evaluate all
// 240 steps and emit per-block partial sums of sqrt(r2).
// ---------------------------------------------------------------------------
__global__ void __launch_bounds__(256) k_xcorr(const float* __restrict__ Dq,
                                               const float* __restrict__ Dp) {
    __shared__ float4 Ps[TI][DIM4];  // 16 KB: the 8 D_p rows of this tile
    __shared__ float  Xs[TI][128];   // X indexed by (k + 61) in [0,121]
    __shared__ float  sP2[TI];       // |P[i]|^2 for the tile

    const int i0   = blockIdx.x * TI;
    const int tid  = threadIdx.x;
    const int warp = tid >> 5;
    const int lane = tid & 31;

    const float4* P4 = (const float4*)Dp;
    const float4* Q4 = (const float4*)Dq;

    // Load 8 P rows into shared (coalesced float4)
    for (int idx = tid; idx < TI * DIM4; idx += 256) {
        int t = idx >> 7, c = idx & 127;
        Ps[t][c] = P4[(i0 + t) * DIM4 + c];
    }
    __syncthreads();

    // warp w computes P2 for bin t = w
    {
        float4 p0 = Ps[warp][lane], p1 = Ps[warp][lane + 32],
               p2 = Ps[warp][lane + 64], p3 = Ps[warp][lane + 96];
        float s = dot4(p0, p0) + dot4(p1, p1) + dot4(p2, p2) + dot4(p3, p3);
        #pragma unroll
        for (int off = 16; off; off >>= 1) s += __shfl_xor_sync(0xffffffffu, s, off);
        if (lane == 0) sP2[warp] = s;
    }

    // Stream the 129-row Q window in 2-row batches per warp.
    // Warp w handles rows base = 2w + 16g, base+1. Rows >= WIN are harmless:
    // their kk falls out of [0, NK) and is never written.
    for (int base = warp * 2; base <= 128; base += 16) {
        const int ra = base, rb = base + 1;
        const float4* qa = Q4 + (((i0 - 60 + ra) & NMASK) * DIM4);
        const float4* qb = Q4 + (((i0 - 60 + rb) & NMASK) * DIM4);
        float4 a0 = qa[lane], a1 = qa[lane + 32], a2 = qa[lane + 64], a3 = qa[lane + 96];
        float4 b0 = qb[lane], b1 = qb[lane + 32], b2 = qb[lane + 64], b3 = qb[lane + 96];
        float accA[TI], accB[TI];
        #pragma unroll
        for (int t = 0; t < TI; t++) {
            float4 p0 = Ps[t][lane], p1 = Ps[t][lane + 32],
                   p2 = Ps[t][lane + 64], p3 = Ps[t][lane + 96];
            accA[t] = dot4(a0, p0) + dot4(a1, p1) + dot4(a2, p2) + dot4(a3, p3);
            accB[t] = dot4(b0, p0) + dot4(b1, p1) + dot4(b2, p2) + dot4(b3, p3);
        }
        #pragma unroll
        for (int t = 0; t < TI; t++) {
            float va = accA[t], vb = accB[t];
            #pragma unroll
            for (int off = 16; off; off >>= 1) {
                va += __shfl_xor_sync(0xffffffffu, va, off);
                vb += __shfl_xor_sync(0xffffffffu, vb, off);
            }
            if (lane == 0) {
                int kka = t + 121 - ra;      // = k + 61
                int kkb = kka - 1;
                if (kka >= 0 && kka < NK) Xs[t][kka] = va;
                if (kkb >= 0 && kkb < NK) Xs[t][kkb] = vb;
            }
        }
    }
    __syncthreads();

    // Evaluate all 240 steps for the 8 bins; thread s accumulates over its bins.
    if (tid < NSTEPS) {
        const int s = tid;
        int k0, k1; float alpha; bool pos;
        if (s < 120) {                         // steps 0.0, 0.5, ..., 59.5
            k0 = s >> 1; k1 = k0 + 1;
            alpha = (s & 1) ? 0.5f : 0.0f;
            pos = true;
        } else {                               // steps -1.0, -1.5, ..., -60.5
            int u = s - 120;
            k0 = -(1 + (u >> 1)); k1 = k0 - 1;
            alpha = (u & 1) ? 0.5f : 0.0f;
            pos = false;
        }
        const float w0 = 1.0f - alpha, w1 = alpha;
        const float w00 = w0 * w0, w11 = w1 * w1, w01 = 2.0f * w0 * w1;
        float acc = 0.0f;
        #pragma unroll
        for (int t = 0; t < TI; t++) {
            int i  = i0 + t;
            int j0 = (i - k0) & NMASK;
            int j1 = (i - k1) & NMASK;
            float adot = pos ? g_A[j0] : g_A[j1];  // Q[j0].Q[j1] (adjacent rows)
            float x0 = Xs[t][k0 + 61];
            float x1 = Xs[t][k1 + 61];
            float r2 = sP2[t] + w00 * g_Q2[j0] + w11 * g_Q2[j1]
                     + w01 * adot - 2.0f * (w0 * x0 + w1 * x1);
            acc += sqrtf(fmaxf(r2, 0.0f));
        }
        g_bpart[s * NBLK + blockIdx.x] = acc;
    }
}

// ---------------------------------------------------------------------------
// Kernel B: dist[s] = mean over bins; argmin with first-index tie-break.
// Packed 64-bit key (float bits << 32 | idx): positive-float bit order ==
// numeric order, so min(key) gives min dist with smallest index on ties.
// ---------------------------------------------------------------------------
__global__ void k_final(float* __restrict__ out) {
    const int tid = threadIdx.x;  // 256 threads
    unsigned long long key = ~0ull;
    if (tid < NSTEPS) {
        const float4* bp = (const float4*)(g_bpart + tid * NBLK);
        float s0 = 0.f, s1 = 0.f, s2 = 0.f, s3 = 0.f;
        #pragma unroll
        for (int c = 0; c < NBLK / 4; c += 4) {
            float4 v0 = bp[c], v1 = bp[c + 1], v2 = bp[c + 2], v3 = bp[c + 3];
            s0 += v0.x + v0.y + v0.z + v0.w;
            s1 += v1.x + v1.y + v1.z + v1.w;
            s2 += v2.x + v2.y + v2.z + v2.w;
            s3 += v3.x + v3.y + v3.z + v3.w;
        }
        float dist = (s0 + s1 + s2 + s3) * (1.0f / (float)N_BINS);
        key = ((unsigned long long)__float_as_uint(dist) << 32) | (unsigned)tid;
    }
    #pragma unroll
    for (int off = 16; off; off >>= 1) {
        unsigned long long o = __shfl_xor_sync(0xffffffffu, key, off);
        if (o < key) key = o;
    }
    __shared__ unsigned long long wk[8];
    if ((tid & 31) == 0) wk[tid >> 5] = key;
    __syncthreads();
    if (tid == 0) {
        unsigned long long best = wk[0];
        #pragma unroll
        for (int w = 1; w < 8; w++) if (wk[w] < best) best = wk[w];
        int bi = (int)(best & 0xffffffffull);
        float dist = __uint_as_float((unsigned)(best >> 32));
        float step = (bi < 120) ? 0.5f * (float)bi : -(1.0f + 0.5f * (float)(bi - 120));
        out[0] = step;
        out[1] = dist;
    }
}

extern "C" void kernel_launch(void* const* d_in, const int* in_sizes, int n_in,
                              void* d_out, int out_size) {
    const float* Dq = (const float*)d_in[0];  // D_q [1024, 512]
    const float* Dp = (const float*)d_in[1];  // D_p [1024, 512]
    float* out = (float*)d_out;

    k_rowstats<<<N_BINS, 64>>>(Dq);
    k_xcorr<<<NBLK, 256>>>(Dq, Dp);
    k_final<<<1, 256>>>(out);
}

// round 3
// speedup vs baseline: 1.3325x; 1.3325x over previous
#include <cuda_runtime.h>
#include <math.h>

#define N_BINS 1024
#define NMASK  (N_BINS - 1)
#define DIM    512
#define DIM4   128            // DIM / 4 (float4 units)
#define NSTEPS 240
#define NK     122            // lags k in [-61, 60]
#define TI     8              // bins per block
#define NBLK   (N_BINS / TI)  // 128 blocks
#define NTHREADS 512
#define NWARPS   16
#define ROWS_PER_WARP 9       // window rows 0..128 covered by 16 warps

// Scratch (device globals; no allocations allowed)
__device__ float g_bpart[NSTEPS * NBLK];   // per-(step, block) partial sums

__device__ __forceinline__ float dot4(float4 a, float4 b) {
    return a.x * b.x + a.y * b.y + a.z * b.z + a.w * b.w;
}

// ---------------------------------------------------------------------------
// k_main: one block per 8-bin tile.
//   Phase 1: load 8 D_p rows to smem, compute |P|^2 per bin.
//   Phase 2: stream the 130-row Q window (rows -1..128 rel. to i0-60) in
//            consecutive 2-row batches per warp; produce
//              Xs[t][k+61] = P[i0+t] . Q[j]            (banded cross-corr)
//              sQ2[r]      = |Q[j]|^2
//              sA[r]       = Q[j] . Q[j-1]
//            using register-resident prev-row (stats are free rides).
//   Phase 3: evaluate all 240 fractional steps, emit per-block partial sums.
// ---------------------------------------------------------------------------
__global__ void __launch_bounds__(NTHREADS) k_main(const float* __restrict__ Dq,
                                                   const float* __restrict__ Dp) {
    __shared__ float4 Ps[TI][DIM4];  // 16 KB
    __shared__ float  Xs[TI][128];   // 4 KB, index kk = k + 61 in [0,121]
    __shared__ float  sQ2[136];      // window rows 0..128 used
    __shared__ float  sA[136];
    __shared__ float  sP2[TI];

    const int i0   = blockIdx.x * TI;
    const int tid  = threadIdx.x;
    const int warp = tid >> 5;
    const int lane = tid & 31;

    const float4* P4 = (const float4*)Dp;
    const float4* Q4 = (const float4*)Dq;

    // ---- Phase 1: P rows to smem --------------------------------------
    for (int idx = tid; idx < TI * DIM4; idx += NTHREADS) {
        int t = idx >> 7, c = idx & 127;
        Ps[t][c] = P4[(i0 + t) * DIM4 + c];
    }
    __syncthreads();

    if (warp < TI) {  // warp w -> |P[i0+w]|^2
        float4 p0 = Ps[warp][lane], p1 = Ps[warp][lane + 32],
               p2 = Ps[warp][lane + 64], p3 = Ps[warp][lane + 96];
        float s = dot4(p0, p0) + dot4(p1, p1) + dot4(p2, p2) + dot4(p3, p3);
        #pragma unroll
        for (int off = 16; off; off >>= 1) s += __shfl_xor_sync(0xffffffffu, s, off);
        if (lane == 0) sP2[warp] = s;
    }

    // ---- Phase 2: Q window streaming ----------------------------------
    // Warp w covers rows [9w, 9w+9] (overlap row 9w+9 with warp w+1 writes
    // identical values -> benign). prev = row 9w-1 seeds the A chain.
    {
        const int base = ROWS_PER_WARP * warp;
        const float4* qp = Q4 + (((i0 - 61 + base) & NMASK) * DIM4);  // row base-1
        float4 pv0 = qp[lane], pv1 = qp[lane + 32], pv2 = qp[lane + 64], pv3 = qp[lane + 96];

        #pragma unroll
        for (int m = 0; m < 5; m++) {
            const int ra = base + 2 * m;
            if (ra <= 128) {
                const int rb = ra + 1;
                const float4* qa = Q4 + (((i0 - 60 + ra) & NMASK) * DIM4);
                const float4* qb = Q4 + (((i0 - 60 + rb) & NMASK) * DIM4);
                float4 a0 = qa[lane], a1 = qa[lane + 32], a2 = qa[lane + 64], a3 = qa[lane + 96];
                float4 b0 = qb[lane], b1 = qb[lane + 32], b2 = qb[lane + 64], b3 = qb[lane + 96];

                // stats (free: rows already in regs)
                float q2a = dot4(a0, a0) + dot4(a1, a1) + dot4(a2, a2) + dot4(a3, a3);
                float q2b = dot4(b0, b0) + dot4(b1, b1) + dot4(b2, b2) + dot4(b3, b3);
                float aa  = dot4(a0, pv0) + dot4(a1, pv1) + dot4(a2, pv2) + dot4(a3, pv3);
                float ab  = dot4(b0, a0) + dot4(b1, a1) + dot4(b2, a2) + dot4(b3, a3);

                // cross-corr accumulators: v[2t] = row ra vs bin t, v[2t+1] = row rb
                float v[2 * TI];
                #pragma unroll
                for (int t = 0; t < TI; t++) {
                    float4 p0 = Ps[t][lane], p1 = Ps[t][lane + 32],
                           p2 = Ps[t][lane + 64], p3 = Ps[t][lane + 96];
                    v[2 * t]     = dot4(a0, p0) + dot4(a1, p1) + dot4(a2, p2) + dot4(a3, p3);
                    v[2 * t + 1] = dot4(b0, p0) + dot4(b1, p1) + dot4(b2, p2) + dot4(b3, p3);
                }

                // ---- folded multi-array reduction: 16 arrays over 32 lanes.
                // After folding offsets 16,8,4,2 and a final +shfl(1), lane L
                // holds the full sum of array g(L) = bit4 | bit3<<1 | bit2<<2 | bit1<<3.
                float r8[8];
                #pragma unroll
                for (int i = 0; i < 8; i++) {
                    bool hi = (lane & 16) != 0;
                    float mine  = hi ? v[2 * i + 1] : v[2 * i];
                    float other = hi ? v[2 * i]     : v[2 * i + 1];
                    r8[i] = mine + __shfl_xor_sync(0xffffffffu, other, 16);
                }
                float r4[4];
                #pragma unroll
                for (int i = 0; i < 4; i++) {
                    bool hi = (lane & 8) != 0;
                    float mine  = hi ? r8[2 * i + 1] : r8[2 * i];
                    float other = hi ? r8[2 * i]     : r8[2 * i + 1];
                    r4[i] = mine + __shfl_xor_sync(0xffffffffu, other, 8);
                }
                float r2a[2];
                #pragma unroll
                for (int i = 0; i < 2; i++) {
                    bool hi = (lane & 4) != 0;
                    float mine  = hi ? r4[2 * i + 1] : r4[2 * i];
                    float other = hi ? r4[2 * i]     : r4[2 * i + 1];
                    r2a[i] = mine + __shfl_xor_sync(0xffffffffu, other, 4);
                }
                float r1;
                {
                    bool hi = (lane & 2) != 0;
                    float mine  = hi ? r2a[1] : r2a[0];
                    float other = hi ? r2a[0] : r2a[1];
                    r1 = mine + __shfl_xor_sync(0xffffffffu, other, 2);
                }
                r1 += __shfl_xor_sync(0xffffffffu, r1, 1);
                if (!(lane & 1)) {
                    int g   = ((lane >> 4) & 1) | (((lane >> 3) & 1) << 1)
                            | (((lane >> 2) & 1) << 2) | (((lane >> 1) & 1) << 3);
                    int t   = g >> 1;
                    int row = (g & 1) ? rb : ra;
                    int kk  = t + 121 - row;   // k + 61
                    if (kk >= 0 && kk < NK) Xs[t][kk] = r1;
                }

                // ---- stats reduction: 4 arrays (q2a,q2b,aa,ab)
                float s1;
                {
                    bool hi = (lane & 16) != 0;
                    float m0 = hi ? q2b : q2a, o0 = hi ? q2a : q2b;
                    float m1 = hi ? ab  : aa,  o1 = hi ? aa  : ab;
                    float u0 = m0 + __shfl_xor_sync(0xffffffffu, o0, 16);
                    float u1 = m1 + __shfl_xor_sync(0xffffffffu, o1, 16);
                    bool h2 = (lane & 8) != 0;
                    float mm = h2 ? u1 : u0, oo = h2 ? u0 : u1;
                    s1 = mm + __shfl_xor_sync(0xffffffffu, oo, 8);
                }
                s1 += __shfl_xor_sync(0xffffffffu, s1, 4);
                s1 += __shfl_xor_sync(0xffffffffu, s1, 2);
                s1 += __shfl_xor_sync(0xffffffffu, s1, 1);
                // lane group id: bit4 -> (q2 vs A pair member), bit3 -> (A vs Q2)
                if (lane == 0)  sQ2[ra] = s1;
                if (lane == 16 && rb <= 128) sQ2[rb] = s1;
                if (lane == 8)  sA[ra]  = s1;
                if (lane == 24 && rb <= 128) sA[rb]  = s1;

                pv0 = b0; pv1 = b1; pv2 = b2; pv3 = b3;
            }
        }
    }
    __syncthreads();

    // ---- Phase 3: evaluate 240 steps over this block's 8 bins ----------
    if (tid < NSTEPS) {
        const int s = tid;
        int k0, k1; float alpha; bool pos;
        if (s < 120) {                         // steps 0.0, 0.5, ..., 59.5
            k0 = s >> 1; k1 = k0 + 1;
            alpha = (s & 1) ? 0.5f : 0.0f;
            pos = true;
        } else {                               // steps -1.0, -1.5, ..., -60.5
            int u = s - 120;
            k0 = -(1 + (u >> 1)); k1 = k0 - 1;
            alpha = (u & 1) ? 0.5f : 0.0f;
            pos = false;
        }
        const float w0 = 1.0f - alpha, w1 = alpha;
        const float w00 = w0 * w0, w11 = w1 * w1, w01 = 2.0f * w0 * w1;
        float acc = 0.0f;
        #pragma unroll
        for (int t = 0; t < TI; t++) {
            int j0r = t + 60 - k0;             // window-relative row of roll k0
            int j1r = t + 60 - k1;
            float adot = pos ? sA[j0r] : sA[j1r];   // Q[j0].Q[j1] adjacency
            float x0 = Xs[t][k0 + 61];
            float x1 = Xs[t][k1 + 61];
            float r2 = sP2[t] + w00 * sQ2[j0r] + w11 * sQ2[j1r]
                     + w01 * adot - 2.0f * (w0 * x0 + w1 * x1);
            acc += sqrtf(fmaxf(r2, 0.0f));
        }
        g_bpart[s * NBLK + blockIdx.x] = acc;
    }
}

// ---------------------------------------------------------------------------
// k_final: dist[s] = mean over bins; argmin with first-index tie-break via
// packed 64-bit key (positive-float bit order == numeric order).
// Two threads per step, 64 partials each, combined via shfl.
// ---------------------------------------------------------------------------
__global__ void __launch_bounds__(512) k_final(float* __restrict__ out) {
    const int tid = threadIdx.x;
    const int s    = tid >> 1;
    const int half = tid & 1;
    unsigned long long key = ~0ull;
    if (s < NSTEPS) {
        const float4* bp = (const float4*)(g_bpart + s * NBLK + half * (NBLK / 2));
        float s0 = 0.f, s1 = 0.f, s2 = 0.f, s3 = 0.f;
        #pragma unroll
        for (int c = 0; c < NBLK / 8; c += 4) {
            float4 v0 = bp[c], v1 = bp[c + 1], v2 = bp[c + 2], v3 = bp[c + 3];
            s0 += v0.x + v0.y + v0.z + v0.w;
            s1 += v1.x + v1.y + v1.z + v1.w;
            s2 += v2.x + v2.y + v2.z + v2.w;
            s3 += v3.x + v3.y + v3.z + v3.w;
        }
        float mine = (s0 + s1) + (s2 + s3);
        float tot  = mine + __shfl_xor_sync(0xffffffffu, mine, 1);
        float dist = tot * (1.0f / (float)N_BINS);
        key = ((unsigned long long)__float_as_uint(dist) << 32) | (unsigned)s;
    }
    #pragma unroll
    for (int off = 16; off; off >>= 1) {
        unsigned long long o = __shfl_xor_sync(0xffffffffu, key, off);
        if (o < key) key = o;
    }
    __shared__ unsigned long long wk[16];
    if ((tid & 31) == 0) wk[tid >> 5] = key;
    __syncthreads();
    if (tid == 0) {
        unsigned long long best = wk[0];
        #pragma unroll
        for (int w = 1; w < 16; w++) if (wk[w] < best) best = wk[w];
        int bi = (int)(best & 0xffffffffull);
        float dist = __uint_as_float((unsigned)(best >> 32));
        float step = (bi < 120) ? 0.5f * (float)bi : -(1.0f + 0.5f * (float)(bi - 120));
        out[0] = step;
        out[1] = dist;
    }
}

extern "C" void kernel_launch(void* const* d_in, const int* in_sizes, int n_in,
                              void* d_out, int out_size) {
    const float* Dq = (const float*)d_in[0];  // D_q [1024, 512]
    const float* Dp = (const float*)d_in[1];  // D_p [1024, 512]
    float* out = (float*)d_out;

    k_main<<<NBLK, NTHREADS>>>(Dq, Dp);
    k_final<<<1, 512>>>(out);
}

// round 4
// speedup vs baseline: 1.3394x; 1.0052x over previous
#include <cuda_runtime.h>
#include <math.h>

#define N_BINS 1024
#define NMASK  (N_BINS - 1)
#define DIM    512
#define DIM4   128            // DIM / 4 (float4 units)
#define NSTEPS 240
#define NK     122            // lags k in [-61, 60]
#define TI     8              // bins per block
#define NBLK   (N_BINS / TI)  // 128 blocks
#define NTHREADS 512
#define NWARPS   16
#define ROWS_PER_WARP 9       // window rows 0..128 covered by 16 warps

// Scratch (device globals; no allocations allowed)
__device__ float g_bpart[NSTEPS * NBLK];   // per-(step, block) partial sums
__device__ unsigned g_ticket;              // last-block election (reset each launch)

__device__ __forceinline__ float dot4(float4 a, float4 b) {
    return a.x * b.x + a.y * b.y + a.z * b.z + a.w * b.w;
}

// ---------------------------------------------------------------------------
// k_main: one block per 8-bin tile.
//   Phase 1: load 8 D_p rows to smem, compute |P|^2 per bin.
//   Phase 2: stream the 130-row Q window; produce banded X-corr + row stats.
//   Phase 3: evaluate all 240 fractional steps, emit per-block partial sums.
//   Phase 4: LAST block (atomic ticket) reduces all partials -> mean dist per
//            step -> argmin (first-index tie-break) -> writes (step, dist).
// ---------------------------------------------------------------------------
__global__ void __launch_bounds__(NTHREADS) k_main(const float* __restrict__ Dq,
                                                   const float* __restrict__ Dp,
                                                   float* __restrict__ out) {
    __shared__ float4 Ps[TI][DIM4];  // 16 KB
    __shared__ float  Xs[TI][128];   // 4 KB, index kk = k + 61 in [0,121]
    __shared__ float  sQ2[136];      // window rows 0..128 used
    __shared__ float  sA[136];
    __shared__ float  sP2[TI];

    const int i0   = blockIdx.x * TI;
    const int tid  = threadIdx.x;
    const int warp = tid >> 5;
    const int lane = tid & 31;

    const float4* P4 = (const float4*)Dp;
    const float4* Q4 = (const float4*)Dq;

    // ---- Phase 1: P rows to smem --------------------------------------
    for (int idx = tid; idx < TI * DIM4; idx += NTHREADS) {
        int t = idx >> 7, c = idx & 127;
        Ps[t][c] = P4[(i0 + t) * DIM4 + c];
    }
    __syncthreads();

    if (warp < TI) {  // warp w -> |P[i0+w]|^2
        float4 p0 = Ps[warp][lane], p1 = Ps[warp][lane + 32],
               p2 = Ps[warp][lane + 64], p3 = Ps[warp][lane + 96];
        float s = dot4(p0, p0) + dot4(p1, p1) + dot4(p2, p2) + dot4(p3, p3);
        #pragma unroll
        for (int off = 16; off; off >>= 1) s += __shfl_xor_sync(0xffffffffu, s, off);
        if (lane == 0) sP2[warp] = s;
    }

    // ---- Phase 2: Q window streaming ----------------------------------
    // Warp w covers rows [9w, 9w+9] (overlap row with warp w+1 writes
    // identical values -> benign). prev = row 9w-1 seeds the A chain.
    {
        const int base = ROWS_PER_WARP * warp;
        const float4* qp = Q4 + (((i0 - 61 + base) & NMASK) * DIM4);  // row base-1
        float4 pv0 = qp[lane], pv1 = qp[lane + 32], pv2 = qp[lane + 64], pv3 = qp[lane + 96];

        #pragma unroll
        for (int m = 0; m < 5; m++) {
            const int ra = base + 2 * m;
            if (ra <= 128) {
                const int rb = ra + 1;
                const float4* qa = Q4 + (((i0 - 60 + ra) & NMASK) * DIM4);
                const float4* qb = Q4 + (((i0 - 60 + rb) & NMASK) * DIM4);
                float4 a0 = qa[lane], a1 = qa[lane + 32], a2 = qa[lane + 64], a3 = qa[lane + 96];
                float4 b0 = qb[lane], b1 = qb[lane + 32], b2 = qb[lane + 64], b3 = qb[lane + 96];

                // stats (free: rows already in regs)
                float q2a = dot4(a0, a0) + dot4(a1, a1) + dot4(a2, a2) + dot4(a3, a3);
                float q2b = dot4(b0, b0) + dot4(b1, b1) + dot4(b2, b2) + dot4(b3, b3);
                float aa  = dot4(a0, pv0) + dot4(a1, pv1) + dot4(a2, pv2) + dot4(a3, pv3);
                float ab  = dot4(b0, a0) + dot4(b1, a1) + dot4(b2, a2) + dot4(b3, a3);

                // cross-corr accumulators: v[2t] = row ra vs bin t, v[2t+1] = row rb
                float v[2 * TI];
                #pragma unroll
                for (int t = 0; t < TI; t++) {
                    float4 p0 = Ps[t][lane], p1 = Ps[t][lane + 32],
                           p2 = Ps[t][lane + 64], p3 = Ps[t][lane + 96];
                    v[2 * t]     = dot4(a0, p0) + dot4(a1, p1) + dot4(a2, p2) + dot4(a3, p3);
                    v[2 * t + 1] = dot4(b0, p0) + dot4(b1, p1) + dot4(b2, p2) + dot4(b3, p3);
                }

                // ---- folded multi-array reduction: 16 arrays over 32 lanes.
                float r8[8];
                #pragma unroll
                for (int i = 0; i < 8; i++) {
                    bool hi = (lane & 16) != 0;
                    float mine  = hi ? v[2 * i + 1] : v[2 * i];
                    float other = hi ? v[2 * i]     : v[2 * i + 1];
                    r8[i] = mine + __shfl_xor_sync(0xffffffffu, other, 16);
                }
                float r4[4];
                #pragma unroll
                for (int i = 0; i < 4; i++) {
                    bool hi = (lane & 8) != 0;
                    float mine  = hi ? r8[2 * i + 1] : r8[2 * i];
                    float other = hi ? r8[2 * i]     : r8[2 * i + 1];
                    r4[i] = mine + __shfl_xor_sync(0xffffffffu, other, 8);
                }
                float r2a[2];
                #pragma unroll
                for (int i = 0; i < 2; i++) {
                    bool hi = (lane & 4) != 0;
                    float mine  = hi ? r4[2 * i + 1] : r4[2 * i];
                    float other = hi ? r4[2 * i]     : r4[2 * i + 1];
                    r2a[i] = mine + __shfl_xor_sync(0xffffffffu, other, 4);
                }
                float r1;
                {
                    bool hi = (lane & 2) != 0;
                    float mine  = hi ? r2a[1] : r2a[0];
                    float other = hi ? r2a[0] : r2a[1];
                    r1 = mine + __shfl_xor_sync(0xffffffffu, other, 2);
                }
                r1 += __shfl_xor_sync(0xffffffffu, r1, 1);
                if (!(lane & 1)) {
                    int g   = ((lane >> 4) & 1) | (((lane >> 3) & 1) << 1)
                            | (((lane >> 2) & 1) << 2) | (((lane >> 1) & 1) << 3);
                    int t   = g >> 1;
                    int row = (g & 1) ? rb : ra;
                    int kk  = t + 121 - row;   // k + 61
                    if (kk >= 0 && kk < NK) Xs[t][kk] = r1;
                }

                // ---- stats reduction: 4 arrays (q2a,q2b,aa,ab)
                float s1;
                {
                    bool hi = (lane & 16) != 0;
                    float m0 = hi ? q2b : q2a, o0 = hi ? q2a : q2b;
                    float m1 = hi ? ab  : aa,  o1 = hi ? aa  : ab;
                    float u0 = m0 + __shfl_xor_sync(0xffffffffu, o0, 16);
                    float u1 = m1 + __shfl_xor_sync(0xffffffffu, o1, 16);
                    bool h2 = (lane & 8) != 0;
                    float mm = h2 ? u1 : u0, oo = h2 ? u0 : u1;
                    s1 = mm + __shfl_xor_sync(0xffffffffu, oo, 8);
                }
                s1 += __shfl_xor_sync(0xffffffffu, s1, 4);
                s1 += __shfl_xor_sync(0xffffffffu, s1, 2);
                s1 += __shfl_xor_sync(0xffffffffu, s1, 1);
                if (lane == 0)  sQ2[ra] = s1;
                if (lane == 16 && rb <= 128) sQ2[rb] = s1;
                if (lane == 8)  sA[ra]  = s1;
                if (lane == 24 && rb <= 128) sA[rb]  = s1;

                pv0 = b0; pv1 = b1; pv2 = b2; pv3 = b3;
            }
        }
    }
    __syncthreads();

    // ---- Phase 3: evaluate 240 steps over this block's 8 bins ----------
    if (tid < NSTEPS) {
        const int s = tid;
        int k0, k1; float alpha; bool pos;
        if (s < 120) {                         // steps 0.0, 0.5, ..., 59.5
            k0 = s >> 1; k1 = k0 + 1;
            alpha = (s & 1) ? 0.5f : 0.0f;
            pos = true;
        } else {                               // steps -1.0, -1.5, ..., -60.5
            int u = s - 120;
            k0 = -(1 + (u >> 1)); k1 = k0 - 1;
            alpha = (u & 1) ? 0.5f : 0.0f;
            pos = false;
        }
        const float w0 = 1.0f - alpha, w1 = alpha;
        const float w00 = w0 * w0, w11 = w1 * w1, w01 = 2.0f * w0 * w1;
        float acc = 0.0f;
        #pragma unroll
        for (int t = 0; t < TI; t++) {
            int j0r = t + 60 - k0;             // window-relative row of roll k0
            int j1r = t + 60 - k1;
            float adot = pos ? sA[j0r] : sA[j1r];   // Q[j0].Q[j1] adjacency
            float x0 = Xs[t][k0 + 61];
            float x1 = Xs[t][k1 + 61];
            float r2 = sP2[t] + w00 * sQ2[j0r] + w11 * sQ2[j1r]
                     + w01 * adot - 2.0f * (w0 * x0 + w1 * x1);
            acc += sqrtf(fmaxf(r2, 0.0f));
        }
        g_bpart[s * NBLK + blockIdx.x] = acc;
    }

    // ---- Phase 4: last block reduces everything (no second launch) -----
    __threadfence();
    __shared__ bool is_last;
    __syncthreads();                 // all phase-3 stores of this block issued
    if (tid == 0) {
        unsigned t = atomicAdd(&g_ticket, 1u);
        is_last = (t == (unsigned)(NBLK - 1));
        if (is_last) g_ticket = 0;   // reset for next graph replay
    }
    __syncthreads();
    if (!is_last) return;

    // Deterministic mean + argmin (identical summation order every launch).
    const int s    = tid >> 1;       // 2 threads per step, 64 partials each
    const int half = tid & 1;
    unsigned long long key = ~0ull;
    if (s < NSTEPS) {
        const float4* bp = (const float4*)(g_bpart + s * NBLK + half * (NBLK / 2));
        float s0 = 0.f, s1 = 0.f, s2 = 0.f, s3 = 0.f;
        #pragma unroll
        for (int c = 0; c < NBLK / 8; c += 4) {
            float4 v0 = bp[c], v1 = bp[c + 1], v2 = bp[c + 2], v3 = bp[c + 3];
            s0 += v0.x + v0.y + v0.z + v0.w;
            s1 += v1.x + v1.y + v1.z + v1.w;
            s2 += v2.x + v2.y + v2.z + v2.w;
            s3 += v3.x + v3.y + v3.z + v3.w;
        }
        float mine = (s0 + s1) + (s2 + s3);
        float tot  = mine + __shfl_xor_sync(0xffffffffu, mine, 1);
        float dist = tot * (1.0f / (float)N_BINS);
        // positive-float bit order == numeric order; low 32 bits = index so
        // ties resolve to the smallest step index (matches jnp.argmin).
        key = ((unsigned long long)__float_as_uint(dist) << 32) | (unsigned)s;
    }
    #pragma unroll
    for (int off = 16; off; off >>= 1) {
        unsigned long long o = __shfl_xor_sync(0xffffffffu, key, off);
        if (o < key) key = o;
    }
    __shared__ unsigned long long wk[NWARPS];
    if (lane == 0) wk[warp] = key;
    __syncthreads();
    if (tid == 0) {
        unsigned long long best = wk[0];
        #pragma unroll
        for (int w = 1; w < NWARPS; w++) if (wk[w] < best) best = wk[w];
        int bi = (int)(best & 0xffffffffull);
        float dist = __uint_as_float((unsigned)(best >> 32));
        float step = (bi < 120) ? 0.5f * (float)bi : -(1.0f + 0.5f * (float)(bi - 120));
        out[0] = step;
        out[1] = dist;
    }
}

extern "C" void kernel_launch(void* const* d_in, const int* in_sizes, int n_in,
                              void* d_out, int out_size) {
    const float* Dq = (const float*)d_in[0];  // D_q [1024, 512]
    const float* Dp = (const float*)d_in[1];  // D_p [1024, 512]
    float* out = (float*)d_out;

    k_main<<<NBLK, NTHREADS>>>(Dq, Dp, out);
}